// round 16
// baseline (speedup 1.0000x reference)
#include <cuda_runtime.h>
#include <cuda_bf16.h>
#include <math.h>
#include <stdint.h>

#define Bdim   128
#define TU     256
#define TB     128
#define TP     64
#define Hd     512
#define Vd     3000
#define VOOVd  3400
#define PTRd   32
#define XP2    2176      // padded X width (2080 -> 17*128)
#define XR     2080
#define G3H    1536
#define CPSW   3128
#define NEGV   (-1e20f)
#define SC8    (1.f/256.f)   // fp8 operands are stored x16 each
#define BTOT   (Bdim*(TU+TB+TP))
#define PCP    (Bdim*TB)

// ---------------- scratch ----------------
__device__ float g_pre1  [Bdim*Hd];
__device__ float g_score [BTOT];
__device__ float g_gi    [Bdim*G3H];
__device__ float g_gh    [Bdim*G3H];
__device__ float g_hnew  [Bdim*Hd];
__device__ float g_gen   [Bdim*Vd];
__device__ float g_cpraw [PCP];
__device__ uint8_t g_W8a [Hd*Hd];
__device__ uint8_t g_W8b [Hd*Hd];
__device__ uint8_t g_W8c [Hd*Hd];
__device__ uint8_t g_W8hh[G3H*Hd];
__device__ uint8_t g_W8ih[G3H*XP2];
__device__ uint8_t g_W8gn[Vd*Hd];
__device__ uint8_t g_h8  [Bdim*Hd];
__device__ uint8_t g_u8  [Bdim*TU*Hd];
__device__ uint8_t g_b8  [Bdim*TB*Hd];
__device__ uint8_t g_p8  [Bdim*TP*Hd];
__device__ uint8_t g_X8  [Bdim*XP2];
__device__ uint8_t g_hn8 [Bdim*Hd];

// ---------------- helpers ----------------
__device__ __forceinline__ uint32_t smem_u32(const void* p) {
    uint32_t a;
    asm("{ .reg .u64 t; cvta.to.shared.u64 t, %1; cvt.u32.u64 %0, t; }" : "=r"(a) : "l"(p));
    return a;
}
__device__ __forceinline__ void ldmx4(uint32_t* r, uint32_t addr) {
    asm volatile("ldmatrix.sync.aligned.m8n8.x4.shared.b16 {%0,%1,%2,%3}, [%4];"
        : "=r"(r[0]), "=r"(r[1]), "=r"(r[2]), "=r"(r[3]) : "r"(addr));
}
__device__ __forceinline__ void mma8(float* d, const uint32_t* a, const uint32_t* b) {
    asm volatile("mma.sync.aligned.m16n8k32.row.col.f32.e4m3.e4m3.f32 "
        "{%0,%1,%2,%3}, {%4,%5,%6,%7}, {%8,%9}, {%0,%1,%2,%3};"
        : "+f"(d[0]), "+f"(d[1]), "+f"(d[2]), "+f"(d[3])
        : "r"(a[0]), "r"(a[1]), "r"(a[2]), "r"(a[3]), "r"(b[0]), "r"(b[1]));
}
__device__ __forceinline__ void cpa16(uint32_t d, const void* s) {
    asm volatile("cp.async.cg.shared.global [%0], [%1], 16;" :: "r"(d), "l"(s));
}
__device__ __forceinline__ void cpa16z(uint32_t d, const void* s, int sz) {
    asm volatile("cp.async.cg.shared.global [%0], [%1], 16, %2;" :: "r"(d), "l"(s), "r"(sz));
}
#define CPCOMMIT() asm volatile("cp.async.commit_group;" ::: "memory")
#define SWZ(x) ((x) ^ (((x) >> 3) & 0x70))

__device__ __forceinline__ uint16_t cvt2_e4m3(float lo, float hi) {
    uint16_t v;
    asm("cvt.rn.satfinite.e4m3x2.f32 %0, %1, %2;" : "=h"(v) : "f"(hi), "f"(lo));
    return v;
}
__device__ __forceinline__ float2 cvt_e4m3_2f(uint16_t v) {
    uint32_t h2;
    asm("cvt.rn.f16x2.e4m3x2 %0, %1;" : "=r"(h2) : "h"(v));
    __half2 h = *(__half2*)&h2;
    return make_float2(__half2float(h.x), __half2float(h.y));
}

__device__ __forceinline__ float tanh_f(float x) {
    float a = fabsf(x);
    if (a < 0.6f) {
        float t = x * x;
        return x * (1.f + t * (-0.33333334f + t * (0.13333333f +
                    t * (-0.05396825f + t * 0.02186949f))));
    }
    return tanhf(x);
}

// ==================== MODE0 fp8 GEMM (3-stage cp.async) ====================
// C[r, n] = acc*SC8 + add[n]  (grid.y tiles N by 128)
// NS = 2: 2-span dispatch (gi / gh): span 1 uses B2/addp2/ld2/KC2
#define SM_EPI 98304    // 3 stages x 32KB
template<int NS>
__global__ void __launch_bounds__(256, 2)
gemm8(const uint8_t* __restrict__ A0, const uint8_t* __restrict__ A1,
      int lda, int KC,
      const uint8_t* __restrict__ B, int ldb, int Nb,
      const float* __restrict__ addp,
      float* __restrict__ C0, float* __restrict__ C1, int ldc,
      const uint8_t* __restrict__ B2 = nullptr,
      const float* __restrict__ addp2 = nullptr,
      int ld2 = 0, int KC2 = 0)
{
    extern __shared__ __align__(128) char sm[];
    const uint32_t sb = smem_u32(sm);
    float* add_s = (float*)(sm + SM_EPI);

    const int tid = threadIdx.x, wid = tid >> 5, lane = tid & 31;
    const int warpM = wid & 3, warpN = wid >> 2;
    const int nb0 = blockIdx.y * 128;

    const uint8_t *Ag, *Bg;
    const float* addP = addp;
    float* Co;
    int ldaL, ldbL, kcL;
    if (NS == 2) {
        if (blockIdx.x == 0) { Ag = A0; Bg = B;  addP = addp;  Co = C0; ldaL = lda; ldbL = ldb; kcL = KC;  }
        else                 { Ag = A1; Bg = B2; addP = addp2; Co = C1; ldaL = ld2; ldbL = ld2; kcL = KC2; }
    } else {
        Ag = A0; Bg = B; Co = C0; ldaL = lda; ldbL = ldb; kcL = KC;
    }

    if (tid < 128) {
        int c = nb0 + tid;
        add_s[tid] = (c < Nb) ? addP[c] : 0.f;
    }

    auto load_tiles = [&](int st, int k0) {
        const uint32_t sA = sb + st * 32768;
        const uint32_t sB = sA + 16384;
#pragma unroll
        for (int i = 0; i < 4; i++) {
            int c = tid + (i << 8);
            int row = c >> 3, col = (c & 7) << 4;
            cpa16(sA + SWZ(row * 128 + col),
                  Ag + (size_t)row * ldaL + k0 + col);
        }
#pragma unroll
        for (int i = 0; i < 4; i++) {
            int c = tid + (i << 8);
            int row = c >> 3, col = (c & 7) << 4;
            int n = nb0 + row;
            cpa16z(sB + SWZ(row * 128 + col),
                   Bg + (size_t)n * ldbL + k0 + col, (n < Nb) ? 16 : 0);
        }
    };

    float acc[2][8][4];
#pragma unroll
    for (int t = 0; t < 2; t++)
#pragma unroll
        for (int j = 0; j < 8; j++)
#pragma unroll
            for (int q = 0; q < 4; q++) acc[t][j][q] = 0.f;

    load_tiles(0, 0);
    CPCOMMIT();
    if (kcL > 1) { load_tiles(1, 128); CPCOMMIT(); }

    for (int kt = 0; kt < kcL; kt++) {
        if (kt + 2 < kcL) {
            load_tiles((kt + 2) % 3, (kt + 2) * 128);
            CPCOMMIT();
            asm volatile("cp.async.wait_group 2;" ::: "memory");
        } else if (kt + 1 < kcL) {
            asm volatile("cp.async.wait_group 1;" ::: "memory");
        } else {
            asm volatile("cp.async.wait_group 0;" ::: "memory");
        }
        __syncthreads();
        const uint32_t As_b = sb + (kt % 3) * 32768;
        const uint32_t Bs_b = As_b + 16384;
#pragma unroll
        for (int kc = 0; kc < 4; kc++) {
            uint32_t af[2][4];
#pragma unroll
            for (int t = 0; t < 2; t++) {
                int row  = warpM * 32 + t * 16 + (lane & 15);
                int bcol = kc * 32 + ((lane >> 4) << 4);
                ldmx4(af[t], As_b + SWZ(row * 128 + bcol));
            }
            uint32_t bfr[4][4];
#pragma unroll
            for (int g = 0; g < 4; g++) {
                int row  = warpN * 64 + g * 16 + (lane & 7) + ((lane >> 4) << 3);
                int bcol = kc * 32 + (((lane >> 3) & 1) << 4);
                ldmx4(bfr[g], Bs_b + SWZ(row * 128 + bcol));
            }
#pragma unroll
            for (int t = 0; t < 2; t++)
#pragma unroll
                for (int g = 0; g < 4; g++) {
                    mma8(acc[t][2*g],   af[t], &bfr[g][0]);
                    mma8(acc[t][2*g+1], af[t], &bfr[g][2]);
                }
        }
        __syncthreads();
    }

#pragma unroll
    for (int t = 0; t < 2; t++) {
        int r0 = warpM * 32 + t * 16 + (lane >> 2);
#pragma unroll
        for (int j = 0; j < 8; j++) {
            int c = nb0 + warpN * 64 + j * 8 + ((lane & 3) << 1);
            if (c < Nb) {
                float b0v = add_s[c - nb0], b1v = add_s[c + 1 - nb0];
                Co[(size_t)r0 * ldc + c]         = acc[t][j][0] * SC8 + b0v;
                Co[(size_t)r0 * ldc + c + 1]     = acc[t][j][1] * SC8 + b1v;
                Co[(size_t)(r0+8) * ldc + c]     = acc[t][j][2] * SC8 + b0v;
                Co[(size_t)(r0+8) * ldc + c + 1] = acc[t][j][3] * SC8 + b1v;
            }
        }
    }
}

// ==================== A-persistent MODE1 fp8 GEMM ====================
// Block owns 128 rows; A (128x512 fp8) resident in smem; full N=512 computed;
// C[row0 + r] = sum_n tanh(acc*SC8 + add[bi,n]) * mul[bi,n]  (plain store).
// NS = 3: 3-span score dispatch; NS = 1: single span (cpraw).
// smem: A 4x16KB @0, B 2x16KB @65536, epi @98304 (add 1024, mul 1024, rowacc 128)
#define SMP_EPI 98304
#define SMP_SZ  (SMP_EPI + 8704)
template<int NS>
__global__ void __launch_bounds__(256, 2)
gemm8p(const uint8_t* __restrict__ A0, const uint8_t* __restrict__ A1,
       const uint8_t* __restrict__ A2,
       const uint8_t* __restrict__ B,       // weight [512 x 512] fp8, ld = Hd
       const float* __restrict__ addp, int add_per_b,
       const float* __restrict__ mulp, int mul_per_b,
       int Td0, float* __restrict__ C0, float* __restrict__ C1,
       float* __restrict__ C2)
{
    extern __shared__ __align__(128) char sm[];
    const uint32_t sb = smem_u32(sm);
    float* add_s  = (float*)(sm + SMP_EPI);
    float* mul_s  = add_s + 1024;
    float* rowacc = mul_s + 1024;

    const int tid = threadIdx.x, wid = tid >> 5, lane = tid & 31;
    const int warpM = wid & 3, warpN = wid >> 2;

    const uint8_t* Ag;
    float* Co;
    int row0, Tdim;
    if (NS == 3) {
        int bx = blockIdx.x;
        if (bx < 256)      { Ag = A0; Co = C0; row0 = bx * 128;         Tdim = TU; }
        else if (bx < 384) { Ag = A1; Co = C1; row0 = (bx - 256) * 128; Tdim = TB; }
        else               { Ag = A2; Co = C2; row0 = (bx - 384) * 128; Tdim = TP; }
    } else {
        Ag = A0; Co = C0; row0 = blockIdx.x * 128; Tdim = Td0;
    }

    // epi params: 2 row-batches x 512 n
    {
        const int b0 = row0 / Tdim;
        for (int i = tid; i < 1024; i += 256) {
            int bi = i >> 9, n = i & 511;
            int b = b0 + bi; if (b > Bdim - 1) b = Bdim - 1;
            add_s[i] = addp[add_per_b ? (b * Hd + n) : n];
            mul_s[i] = mulp[mul_per_b ? (b * Hd + n) : n];
        }
        if (tid < 128) rowacc[tid] = 0.f;
    }

    // A: 4 chunks of 128x128B, loaded once
#pragma unroll
    for (int kt = 0; kt < 4; kt++) {
#pragma unroll
        for (int i = 0; i < 4; i++) {
            int c = tid + (i << 8);
            int row = c >> 3, col = (c & 7) << 4;
            cpa16(sb + kt * 16384 + SWZ(row * 128 + col),
                  Ag + (size_t)(row0 + row) * Hd + kt * 128 + col);
        }
    }
    // B tile for linear step g: rows [nt*128, +128), cols [kt*128, +128)
    auto loadB = [&](int g) {
        int nt = g >> 2, kt = g & 3;
        uint32_t sB = sb + 65536 + (g & 1) * 16384;
#pragma unroll
        for (int i = 0; i < 4; i++) {
            int c = tid + (i << 8);
            int row = c >> 3, col = (c & 7) << 4;
            cpa16(sB + SWZ(row * 128 + col),
                  B + (size_t)(nt * 128 + row) * Hd + kt * 128 + col);
        }
    };
    loadB(0); CPCOMMIT();    // group 0 = all A + B(0)

    float rs[4] = {0.f, 0.f, 0.f, 0.f};
    for (int nt = 0; nt < 4; nt++) {
        float acc[2][8][4];
#pragma unroll
        for (int t = 0; t < 2; t++)
#pragma unroll
            for (int j = 0; j < 8; j++)
#pragma unroll
                for (int q = 0; q < 4; q++) acc[t][j][q] = 0.f;

        for (int kt = 0; kt < 4; kt++) {
            const int g = nt * 4 + kt;
            if (g + 1 < 16) {
                loadB(g + 1);
                CPCOMMIT();
                asm volatile("cp.async.wait_group 1;" ::: "memory");
            } else {
                asm volatile("cp.async.wait_group 0;" ::: "memory");
            }
            __syncthreads();
            const uint32_t As_b = sb + kt * 16384;
            const uint32_t Bs_b = sb + 65536 + (g & 1) * 16384;
#pragma unroll
            for (int kc = 0; kc < 4; kc++) {
                uint32_t af[2][4];
#pragma unroll
                for (int t = 0; t < 2; t++) {
                    int row  = warpM * 32 + t * 16 + (lane & 15);
                    int bcol = kc * 32 + ((lane >> 4) << 4);
                    ldmx4(af[t], As_b + SWZ(row * 128 + bcol));
                }
                uint32_t bfr[4][4];
#pragma unroll
                for (int gg = 0; gg < 4; gg++) {
                    int row  = warpN * 64 + gg * 16 + (lane & 7) + ((lane >> 4) << 3);
                    int bcol = kc * 32 + (((lane >> 3) & 1) << 4);
                    ldmx4(bfr[gg], Bs_b + SWZ(row * 128 + bcol));
                }
#pragma unroll
                for (int t = 0; t < 2; t++)
#pragma unroll
                    for (int gg = 0; gg < 4; gg++) {
                        mma8(acc[t][2*gg],   af[t], &bfr[gg][0]);
                        mma8(acc[t][2*gg+1], af[t], &bfr[gg][2]);
                    }
            }
            __syncthreads();
        }
        // epilogue for this 128-wide n-slice (overlaps next B load)
#pragma unroll
        for (int t = 0; t < 2; t++) {
            int bi = (warpM * 32 + t * 16) / Tdim;
            const float* aS = add_s + bi * 512 + nt * 128;
            const float* mS = mul_s + bi * 512 + nt * 128;
#pragma unroll
            for (int j = 0; j < 8; j++) {
                int n = warpN * 64 + j * 8 + ((lane & 3) << 1);
                rs[t*2+0] += tanh_f(acc[t][j][0] * SC8 + aS[n])   * mS[n]
                           + tanh_f(acc[t][j][1] * SC8 + aS[n+1]) * mS[n+1];
                rs[t*2+1] += tanh_f(acc[t][j][2] * SC8 + aS[n])   * mS[n]
                           + tanh_f(acc[t][j][3] * SC8 + aS[n+1]) * mS[n+1];
            }
        }
    }
#pragma unroll
    for (int q = 0; q < 4; q++) {
        rs[q] += __shfl_xor_sync(0xffffffffu, rs[q], 1);
        rs[q] += __shfl_xor_sync(0xffffffffu, rs[q], 2);
    }
    if ((lane & 3) == 0) {
#pragma unroll
        for (int t = 0; t < 2; t++) {
            int rloc = warpM * 32 + t * 16 + (lane >> 2);
            atomicAdd(&rowacc[rloc],     rs[t*2+0]);
            atomicAdd(&rowacc[rloc + 8], rs[t*2+1]);
        }
    }
    __syncthreads();
    if (tid < 128) Co[row0 + tid] = rowacc[tid];
}

// ---------------- fused f32 -> e4m3(x16) conversion, 10 jobs ----------------
struct CJob { const float* src; uint8_t* dst; int rows, cols, lds, coff, ldd; };
struct CJobs { CJob j[10]; };

__global__ void __launch_bounds__(256)
conv_all(CJobs js)
{
    CJob J = js.j[blockIdx.y];
    const int w8 = J.ldd >> 3;
    const int nch = J.rows * w8;
    for (int i = blockIdx.x * 256 + threadIdx.x; i < nch; i += gridDim.x * 256) {
        int r = i / w8, c8 = (i - r * w8) << 3;
        uint32_t o0 = 0, o1 = 0;
        if (c8 < J.cols) {
            const float* s = J.src + (size_t)r * J.lds + J.coff + c8;
            float4 f0 = *(const float4*)s;
            float4 f1 = *(const float4*)(s + 4);
            o0 = (uint32_t)cvt2_e4m3(f0.x*16.f, f0.y*16.f)
               | ((uint32_t)cvt2_e4m3(f0.z*16.f, f0.w*16.f) << 16);
            o1 = (uint32_t)cvt2_e4m3(f1.x*16.f, f1.y*16.f)
               | ((uint32_t)cvt2_e4m3(f1.z*16.f, f1.w*16.f) << 16);
        }
        *(uint2*)(J.dst + (size_t)r * J.ldd + c8) = make_uint2(o0, o1);
    }
}

// ---------------- reductions ----------------
__device__ __forceinline__ float block_reduce_max(float val, float* red) {
    int tid = threadIdx.x, nw = blockDim.x >> 5;
    for (int o = 16; o; o >>= 1) val = fmaxf(val, __shfl_down_sync(0xffffffffu, val, o));
    if ((tid & 31) == 0) red[tid >> 5] = val;
    __syncthreads();
    if (tid < 32) {
        val = (tid < nw) ? red[tid] : -3.0e38f;
        for (int o = 16; o; o >>= 1) val = fmaxf(val, __shfl_down_sync(0xffffffffu, val, o));
        if (tid == 0) red[0] = val;
    }
    __syncthreads();
    val = red[0]; __syncthreads();
    return val;
}
__device__ __forceinline__ float block_reduce_sum(float val, float* red) {
    int tid = threadIdx.x, nw = blockDim.x >> 5;
    for (int o = 16; o; o >>= 1) val += __shfl_down_sync(0xffffffffu, val, o);
    if ((tid & 31) == 0) red[tid >> 5] = val;
    __syncthreads();
    if (tid < 32) {
        val = (tid < nw) ? red[tid] : 0.f;
        for (int o = 16; o; o >>= 1) val += __shfl_down_sync(0xffffffffu, val, o);
        if (tid == 0) red[0] = val;
    }
    __syncthreads();
    val = red[0]; __syncthreads();
    return val;
}

// masked softmax + ctx (z<3) + embedding/db/pad (z==3); grid (Bdim,1,4), 512 thr.
__global__ void __launch_bounds__(512)
softmax3_k(const float* __restrict__ score,
           const int* __restrict__ ids_u, const int* __restrict__ ids_b,
           const int* __restrict__ ids_p,
           const uint8_t* __restrict__ e_u, const uint8_t* __restrict__ e_b,
           const uint8_t* __restrict__ e_p,
           uint8_t* __restrict__ X8,
           const int* __restrict__ w, const float* __restrict__ emb,
           const float* __restrict__ db)
{
    const int b = blockIdx.x, z = blockIdx.z, tid = threadIdx.x;
    if (z == 3) {
        int widx = w[b];
        if (tid < 256) {
            const float* e = emb + (size_t)widx * Hd + (tid << 1);
            *(uint16_t*)(X8 + (size_t)b * XP2 + (tid << 1)) =
                cvt2_e4m3(e[0] * 16.f, e[1] * 16.f);
        } else if (tid < 256 + PTRd/2) {
            int i = (tid - 256) << 1;
            const float* d = db + b * PTRd + i;
            *(uint16_t*)(X8 + (size_t)b * XP2 + 2048 + i) =
                cvt2_e4m3(d[0] * 16.f, d[1] * 16.f);
        } else if (tid < 256 + PTRd/2 + (XP2 - XR)/2) {
            int i = (tid - 256 - PTRd/2) << 1;
            *(uint16_t*)(X8 + (size_t)b * XP2 + XR + i) = 0;
        }
        return;
    }

    int T, soff; const int* ids; const uint8_t* enc;
    if (z == 0)      { T = TU; ids = ids_u; enc = e_u; soff = 0; }
    else if (z == 1) { T = TB; ids = ids_b; enc = e_b; soff = Bdim*TU; }
    else             { T = TP; ids = ids_p; enc = e_p; soff = Bdim*(TU+TB); }

    __shared__ float aw[TU];
    __shared__ float red[32];
    __shared__ float part[8 * 512];

    float sv = -3.0e38f;
    if (tid < T) {
        float s = score[soff + b * T + tid];
        if (ids[b * T + tid] == 0) s = NEGV;
        aw[tid] = s; sv = s;
    }
    float m = block_reduce_max(sv, red);
    float e = 0.f;
    if (tid < T) { e = __expf(aw[tid] - m); aw[tid] = e; }
    float ssum = block_reduce_sum(e, red);
    float inv = 1.f / ssum;

    const int tg = tid >> 6;              // 8 t-groups
    const int hc = (tid & 63) << 3;       // 8 h-cols per thread
    float c[8];
#pragma unroll
    for (int k = 0; k < 8; k++) c[k] = 0.f;
    const uint8_t* eb = enc + (size_t)b * T * Hd + hc;
#pragma unroll 4
    for (int t = tg; t < T; t += 8) {
        uint2 v = *(const uint2*)(eb + (size_t)t * Hd);
        float2 f0 = cvt_e4m3_2f((uint16_t)(v.x & 0xffffu));
        float2 f1 = cvt_e4m3_2f((uint16_t)(v.x >> 16));
        float2 f2 = cvt_e4m3_2f((uint16_t)(v.y & 0xffffu));
        float2 f3 = cvt_e4m3_2f((uint16_t)(v.y >> 16));
        float wv = aw[t] * inv;
        c[0] = fmaf(wv, f0.x, c[0]); c[1] = fmaf(wv, f0.y, c[1]);
        c[2] = fmaf(wv, f1.x, c[2]); c[3] = fmaf(wv, f1.y, c[3]);
        c[4] = fmaf(wv, f2.x, c[4]); c[5] = fmaf(wv, f2.y, c[5]);
        c[6] = fmaf(wv, f3.x, c[6]); c[7] = fmaf(wv, f3.y, c[7]);
    }
#pragma unroll
    for (int k = 0; k < 8; k++) part[tg * 512 + hc + k] = c[k];
    __syncthreads();
    float s = part[tid];
#pragma unroll
    for (int g = 1; g < 8; g++) s += part[g * 512 + tid];
    part[tid] = s;
    __syncthreads();
    if (tid < 128) {
        int h0 = tid << 2;
        uint32_t o = (uint32_t)cvt2_e4m3(part[h0], part[h0+1])
                   | ((uint32_t)cvt2_e4m3(part[h0+2], part[h0+3]) << 16);
        *(uint32_t*)(X8 + (size_t)b * XP2 + Hd * (z + 1) + h0) = o;
    }
}

__global__ void gate_k(const float* __restrict__ gi, const float* __restrict__ gh,
                       const float* __restrict__ h0, float* __restrict__ hnew,
                       uint8_t* __restrict__ hn8)
{
    int b = blockIdx.x, h = threadIdx.x;
    float ir  = gi[b*G3H + h],        hr = gh[b*G3H + h];
    float iz  = gi[b*G3H + Hd + h],   hz = gh[b*G3H + Hd + h];
    float inn = gi[b*G3H + 2*Hd + h], hn = gh[b*G3H + 2*Hd + h];
    float rr = 1.f / (1.f + __expf(-(ir + hr)));
    float z  = 1.f / (1.f + __expf(-(iz + hz)));
    float n  = tanhf(inn + rr * hn);
    float v  = (1.f - z) * n + z * h0[b*Hd + h];
    hnew[b*Hd + h] = v;
    uint16_t p = cvt2_e4m3(v * 16.f, 0.f);
    hn8[b*Hd + h] = (uint8_t)(p & 0xff);
}

// final: build cps in smem from cpraw, single-exp log-softmax + OOV
__global__ void __launch_bounds__(1024)
final_k(const float* __restrict__ gen, const float* __restrict__ cpraw,
        const int* __restrict__ bids, const int* __restrict__ nounk,
        float* __restrict__ out)
{
    const int b = blockIdx.x, tid = threadIdx.x;
    const float* gb = gen + (size_t)b * Vd;
    __shared__ float red[32];
    __shared__ float adds[VOOVd - Vd];
    __shared__ float cps_s[CPSW];
    __shared__ float eg_s[Vd];

    for (int i = tid; i < CPSW; i += 1024) cps_s[i] = 0.f;
    __syncthreads();
    if (tid < TB) {
        int idx = b * TB + tid;
        float val = cpraw[idx];
        if (bids[idx] == 0) val = NEGV;
        int nk = nounk[idx];
        int col = (nk < Vd) ? nk : (Vd + tid);
        atomicAdd(&cps_s[col], val);
    }
    __syncthreads();

    float m = -3.0e38f;
    for (int i = tid; i < Vd;   i += 1024) m = fmaxf(m, gb[i]);
    for (int i = tid; i < CPSW; i += 1024) m = fmaxf(m, cps_s[i]);
    m = block_reduce_max(m, red);

    float s = 0.f;
    for (int i = tid; i < Vd; i += 1024) {
        float e = __expf(gb[i] - m);
        eg_s[i] = e; s += e;
    }
    for (int i = tid; i < CPSW; i += 1024) {
        float e = __expf(cps_s[i] - m);
        cps_s[i] = e; s += e;
    }
    s = block_reduce_sum(s, red);
    float logS = __logf(s);

    for (int i = tid; i < Vd; i += 1024)
        out[(size_t)b*VOOVd + i] = __logf(eg_s[i] + cps_s[i]) - logS;

    for (int i = tid; i < (VOOVd - Vd); i += 1024) adds[i] = 0.f;
    __syncthreads();
    if (tid < TB) {
        int nk = nounk[b*TB + tid];
        if (nk >= Vd) atomicAdd(&adds[nk - Vd], cps_s[Vd + tid] / s);
    }
    __syncthreads();
    for (int i = tid; i < (VOOVd - Vd); i += 1024) {
        float a = adds[i];
        out[(size_t)b*VOOVd + Vd + i] = (a > 0.f) ? __logf(fmaxf(a, 1e-38f)) : NEGV;
    }
}

// =============================== host ======================================
#define SMEMSZ (SM_EPI + 2560)

extern "C" void kernel_launch(void* const* d_in, const int* in_sizes, int n_in,
                              void* d_out, int out_size)
{
    (void)in_sizes; (void)n_in; (void)out_size;
    const int*   dec_last_w = (const int*)  d_in[0];
    const float* dec_last_h = (const float*)d_in[1];
    const float* usdx_h     = (const float*)d_in[2];
    const float* bspn_h     = (const float*)d_in[3];
    const float* pvaspn_h   = (const float*)d_in[4];
    const float* db         = (const float*)d_in[5];
    const int*   usdx_ids   = (const int*)  d_in[6];
    const int*   bspn_ids   = (const int*)  d_in[7];
    const int*   pvaspn_ids = (const int*)  d_in[8];
    const int*   bspn_nounk = (const int*)  d_in[9];
    /* d_in[10] bspn_onehot unused */
    const float* emb_table  = (const float*)d_in[11];
    const float* attn_W     = (const float*)d_in[12];
    const float* attn_b     = (const float*)d_in[13];
    const float* v_w        = (const float*)d_in[14];
    const float* Wcopy_w    = (const float*)d_in[15];
    const float* Wcopy_b    = (const float*)d_in[16];
    const float* Wgen_w     = (const float*)d_in[17];
    const float* Wgen_b     = (const float*)d_in[18];
    const float* W_ih       = (const float*)d_in[19];
    const float* W_hh       = (const float*)d_in[20];
    const float* b_ih       = (const float*)d_in[21];
    const float* b_hh       = (const float*)d_in[22];
    float* out = (float*)d_out;

    float *pre1,*score,*gi,*gh,*hnew,*gen,*cpraw;
    uint8_t *W8a,*W8b,*W8c,*W8hh,*W8ih,*W8gn,*h8,*u8,*b8,*p8,*X8,*hn8;
    cudaGetSymbolAddress((void**)&pre1,   g_pre1);
    cudaGetSymbolAddress((void**)&score,  g_score);
    cudaGetSymbolAddress((void**)&gi,     g_gi);
    cudaGetSymbolAddress((void**)&gh,     g_gh);
    cudaGetSymbolAddress((void**)&hnew,   g_hnew);
    cudaGetSymbolAddress((void**)&gen,    g_gen);
    cudaGetSymbolAddress((void**)&cpraw,  g_cpraw);
    cudaGetSymbolAddress((void**)&W8a,    g_W8a);
    cudaGetSymbolAddress((void**)&W8b,    g_W8b);
    cudaGetSymbolAddress((void**)&W8c,    g_W8c);
    cudaGetSymbolAddress((void**)&W8hh,   g_W8hh);
    cudaGetSymbolAddress((void**)&W8ih,   g_W8ih);
    cudaGetSymbolAddress((void**)&W8gn,   g_W8gn);
    cudaGetSymbolAddress((void**)&h8,     g_h8);
    cudaGetSymbolAddress((void**)&u8,     g_u8);
    cudaGetSymbolAddress((void**)&b8,     g_b8);
    cudaGetSymbolAddress((void**)&p8,     g_p8);
    cudaGetSymbolAddress((void**)&X8,     g_X8);
    cudaGetSymbolAddress((void**)&hn8,    g_hn8);

    cudaFuncSetAttribute(gemm8<1>,  cudaFuncAttributeMaxDynamicSharedMemorySize, SMEMSZ);
    cudaFuncSetAttribute(gemm8<2>,  cudaFuncAttributeMaxDynamicSharedMemorySize, SMEMSZ);
    cudaFuncSetAttribute(gemm8p<1>, cudaFuncAttributeMaxDynamicSharedMemorySize, SMP_SZ);
    cudaFuncSetAttribute(gemm8p<3>, cudaFuncAttributeMaxDynamicSharedMemorySize, SMP_SZ);

    // 1: all f32 -> fp8(x16) conversions
    CJobs js;
    js.j[0] = { attn_W,     W8a,  Hd,      Hd, 2*Hd, 0,  Hd  };
    js.j[1] = { attn_W,     W8b,  Hd,      Hd, 2*Hd, Hd, Hd  };
    js.j[2] = { Wcopy_w,    W8c,  Hd,      Hd, Hd,   0,  Hd  };
    js.j[3] = { W_hh,       W8hh, G3H,     Hd, Hd,   0,  Hd  };
    js.j[4] = { W_ih,       W8ih, G3H,     XR, XR,   0,  XP2 };
    js.j[5] = { Wgen_w,     W8gn, Vd,      Hd, Hd,   0,  Hd  };
    js.j[6] = { dec_last_h, h8,   Bdim,    Hd, Hd,   0,  Hd  };
    js.j[7] = { usdx_h,     u8,   Bdim*TU, Hd, Hd,   0,  Hd  };
    js.j[8] = { bspn_h,     b8,   Bdim*TB, Hd, Hd,   0,  Hd  };
    js.j[9] = { pvaspn_h,   p8,   Bdim*TP, Hd, Hd,   0,  Hd  };
    conv_all<<<dim3(1024, 10), 256>>>(js);

    // 2: pre1 = h0 @ Wa^T + attn_b
    gemm8<1><<<dim3(1,4), 256, SMEMSZ>>>(h8, nullptr, Hd, 4,
        W8a, Hd, Hd, attn_b, pre1, nullptr, Hd);

    // 3: ALL attention scores (A-persistent, full-N, plain store)
    gemm8p<3><<<448, 256, SMP_SZ>>>(u8, b8, p8, W8b,
        pre1, 1, v_w, 0, 0,
        score, score + Bdim*TU, score + Bdim*(TU+TB));

    // 4: softmax + ctx (+ emb/db/pad as z=3)
    softmax3_k<<<dim3(Bdim,1,4), 512>>>(score, usdx_ids, bspn_ids, pvaspn_ids,
                                        u8, b8, p8, X8, dec_last_w, emb_table, db);

    // 5: gi = X@W_ih^T + b_ih  AND  gh = h0@W_hh^T + b_hh  (merged, NS=2)
    gemm8<2><<<dim3(2,12), 256, SMEMSZ>>>(X8, h8, XP2, 17,
        W8ih, XP2, G3H, b_ih, gi, gh, G3H,
        W8hh, b_hh, Hd, 4);

    // 6: gate
    gate_k<<<Bdim, Hd>>>(gi, gh, dec_last_h, hnew, hn8);

    // 7: gen = hnew @ Wgen^T + b
    gemm8<1><<<dim3(1,24), 256, SMEMSZ>>>(hn8, nullptr, Hd, 4,
        W8gn, Hd, Vd, Wgen_b, gen, nullptr, Vd);

    // 8: cp_raw = sum_h tanh(bspn_h@Wcopy^T + b) * hnew  (A-persistent)
    gemm8p<1><<<128, 256, SMP_SZ>>>(b8, nullptr, nullptr, W8c,
        Wcopy_b, 0, hnew, 1, TB, cpraw, nullptr, nullptr);

    // 9: final (cps built in smem; scatter fused; single-exp)
    final_k<<<Bdim, 1024>>>(gen, cpraw, bspn_ids, bspn_nounk, out);
}

// round 17
// speedup vs baseline: 1.2726x; 1.2726x over previous
#include <cuda_runtime.h>
#include <cuda_bf16.h>
#include <math.h>
#include <stdint.h>

#define Bdim   128
#define TU     256
#define TB     128
#define TP     64
#define Hd     512
#define Vd     3000
#define VOOVd  3400
#define PTRd   32
#define XP2    2176      // padded X width (2080 -> 17*128)
#define XR     2080
#define G3H    1536
#define CPSW   3128
#define NEGV   (-1e20f)
#define SC8    (1.f/256.f)   // fp8 operands are stored x16 each
#define BTOT   (Bdim*(TU+TB+TP))
#define PCP    (Bdim*TB)
#define PRE1S  (Bdim*Hd)     // pre1 K-partial stride
#define GIS    (Bdim*G3H)    // gi/gh K-partial stride

// ---------------- scratch ----------------
__device__ float g_pre1  [2*PRE1S];
__device__ float g_score4[4*BTOT];
__device__ float g_gi    [3*GIS];
__device__ float g_gh    [3*GIS];
__device__ float g_hnew  [Bdim*Hd];
__device__ float g_gen   [Bdim*Vd];
__device__ float g_cpraw4[4*PCP];
__device__ uint8_t g_W8a [Hd*Hd];
__device__ uint8_t g_W8b [Hd*Hd];
__device__ uint8_t g_W8c [Hd*Hd];
__device__ uint8_t g_W8hh[G3H*Hd];
__device__ uint8_t g_W8ih[G3H*XP2];
__device__ uint8_t g_W8gn[Vd*Hd];
__device__ uint8_t g_h8  [Bdim*Hd];
__device__ uint8_t g_u8  [Bdim*TU*Hd];
__device__ uint8_t g_b8  [Bdim*TB*Hd];
__device__ uint8_t g_p8  [Bdim*TP*Hd];
__device__ uint8_t g_X8  [Bdim*XP2];
__device__ uint8_t g_hn8 [Bdim*Hd];

// ---------------- helpers ----------------
__device__ __forceinline__ uint32_t smem_u32(const void* p) {
    uint32_t a;
    asm("{ .reg .u64 t; cvta.to.shared.u64 t, %1; cvt.u32.u64 %0, t; }" : "=r"(a) : "l"(p));
    return a;
}
__device__ __forceinline__ void ldmx4(uint32_t* r, uint32_t addr) {
    asm volatile("ldmatrix.sync.aligned.m8n8.x4.shared.b16 {%0,%1,%2,%3}, [%4];"
        : "=r"(r[0]), "=r"(r[1]), "=r"(r[2]), "=r"(r[3]) : "r"(addr));
}
__device__ __forceinline__ void mma8(float* d, const uint32_t* a, const uint32_t* b) {
    asm volatile("mma.sync.aligned.m16n8k32.row.col.f32.e4m3.e4m3.f32 "
        "{%0,%1,%2,%3}, {%4,%5,%6,%7}, {%8,%9}, {%0,%1,%2,%3};"
        : "+f"(d[0]), "+f"(d[1]), "+f"(d[2]), "+f"(d[3])
        : "r"(a[0]), "r"(a[1]), "r"(a[2]), "r"(a[3]), "r"(b[0]), "r"(b[1]));
}
__device__ __forceinline__ void cpa16(uint32_t d, const void* s) {
    asm volatile("cp.async.cg.shared.global [%0], [%1], 16;" :: "r"(d), "l"(s));
}
__device__ __forceinline__ void cpa16z(uint32_t d, const void* s, int sz) {
    asm volatile("cp.async.cg.shared.global [%0], [%1], 16, %2;" :: "r"(d), "l"(s), "r"(sz));
}
#define CPCOMMIT() asm volatile("cp.async.commit_group;" ::: "memory")
#define SWZ(x) ((x) ^ (((x) >> 3) & 0x70))

__device__ __forceinline__ uint16_t cvt2_e4m3(float lo, float hi) {
    uint16_t v;
    asm("cvt.rn.satfinite.e4m3x2.f32 %0, %1, %2;" : "=h"(v) : "f"(hi), "f"(lo));
    return v;
}
__device__ __forceinline__ float2 cvt_e4m3_2f(uint16_t v) {
    uint32_t h2;
    asm("cvt.rn.f16x2.e4m3x2 %0, %1;" : "=r"(h2) : "h"(v));
    __half2 h = *(__half2*)&h2;
    return make_float2(__half2float(h.x), __half2float(h.y));
}

__device__ __forceinline__ float tanh_f(float x) {
    float a = fabsf(x);
    if (a < 0.6f) {
        float t = x * x;
        return x * (1.f + t * (-0.33333334f + t * (0.13333333f +
                    t * (-0.05396825f + t * 0.02186949f))));
    }
    return tanhf(x);
}

// ==================== fp8 mma.sync GEMM (3-stage cp.async) ====================
// C = A[M x K] @ B[Nb x K]^T, e4m3 (x16 each) -> acc * 1/256.
// MODE 0: C[r, n] = acc*SC8 + add[n]*(zk==0)       (grid.y tiles N)
// MODE 1: C[ny*Pstride + r] = sum_n tanh(acc*SC8+addsum[bi,n])*mul[bi,n]
// MODE 3 + NS 4: merged gen (MODE0 sub) + cpraw (MODE1 sub)
// NS = 3: MODE1 3-span dispatch (usdx/bspn/pvaspn)
// NS = 2: MODE0 2-span dispatch (gi / gh)
// NZ > 1: K split into NZ chunks over blockIdx.z; MODE0 output += zk*KPstride
#define SM_EPI 98304    // 3 stages x 32KB
template<int MODE, int NS, int NZ>
__global__ void __launch_bounds__(256, 2)
gemm8(const uint8_t* __restrict__ A0, const uint8_t* __restrict__ A1,
      const uint8_t* __restrict__ A2,
      int lda, int KC,
      const uint8_t* __restrict__ B, int ldb, int Nb,
      const float* __restrict__ addp, int add_per_b,
      const float* __restrict__ mulp, int mul_per_b,
      int Td0, float* __restrict__ C0, float* __restrict__ C1,
      float* __restrict__ C2, int ldc, int Pstride,
      const uint8_t* __restrict__ B2 = nullptr,
      const float* __restrict__ addp2 = nullptr,
      int ld2 = 0, int KC2 = 0,
      int KPstride = 0, int addParts = 1, int addStride = 0)
{
    extern __shared__ __align__(128) char sm[];
    const uint32_t sb = smem_u32(sm);
    float* add_s  = (float*)(sm + SM_EPI);
    float* mul_s  = add_s + 256;
    float* rowacc = add_s + 512;

    const int tid = threadIdx.x, wid = tid >> 5, lane = tid & 31;
    const int warpM = wid & 3, warpN = wid >> 2;
    const int zk = (NZ > 1) ? blockIdx.z : 0;

    const uint8_t *Ag, *Bg;
    const float* addP = addp;
    float* Co;
    int row0, Tdim, ldaL, ldbL, kcL, NbL = Nb;
    int nb0 = blockIdx.y * 128;
    bool isGen = (MODE == 0);
    if (NS == 3) {
        int bx = blockIdx.x;
        if (bx < 256)      { Ag = A0; Co = C0; row0 = bx * 128;         Tdim = TU; }
        else if (bx < 384) { Ag = A1; Co = C1; row0 = (bx - 256) * 128; Tdim = TB; }
        else               { Ag = A2; Co = C2; row0 = (bx - 384) * 128; Tdim = TP; }
        Bg = B; ldaL = lda; ldbL = ldb; kcL = KC;
    } else if (NS == 2) {
        row0 = 0; Tdim = Td0;
        if (blockIdx.x == 0) { Ag = A0; Bg = B;  addP = addp;  Co = C0; ldaL = lda; ldbL = ldb; kcL = KC;  }
        else                 { Ag = A1; Bg = B2; addP = addp2; Co = C1; ldaL = ld2; ldbL = ld2; kcL = KC2; }
    } else if (NS == 4) {
        int bx = blockIdx.x;
        Tdim = Td0;
        if (bx < 24) {
            isGen = true;
            Ag = A0; Bg = B; addP = addp; Co = C0;
            row0 = 0; nb0 = bx * 128;
            ldaL = lda; ldbL = ldb; kcL = KC; NbL = Nb;
        } else {
            isGen = false;
            int i = bx - 24;
            Ag = A1; Bg = B2; addP = addp2; Co = C1;
            row0 = (i >> 2) * 128; nb0 = (i & 3) * 128;
            ldaL = ld2; ldbL = ld2; kcL = KC2; NbL = Hd;
        }
    } else {
        Ag = A0; Co = C0; row0 = blockIdx.x * 128; Tdim = Td0;
        Bg = B; ldaL = lda; ldbL = ldb; kcL = KC;
    }
    if (NZ > 1) Co += (size_t)zk * KPstride;

    // K-chunk range for this z
    int cpb = (kcL + NZ - 1) / NZ;
    int kc0 = (NZ > 1) ? zk * cpb : 0;
    int kcN = (NZ > 1) ? min(kcL, kc0 + cpb) : kcL;
    const int L = kcN - kc0;

    if (isGen) {
        if (tid < 128) {
            int c = nb0 + tid;
            add_s[tid] = (c < NbL && zk == 0) ? addP[c] : 0.f;
        }
    } else {
        const int b0 = row0 / Tdim;
        {
            int bi = tid >> 7, nl = tid & 127;
            int b = b0 + bi; if (b > Bdim - 1) b = Bdim - 1;
            int base = add_per_b ? (b * Hd + nb0 + nl) : (nb0 + nl);
            float av = 0.f;
            for (int p = 0; p < addParts; p++) av += addP[base + p * addStride];
            add_s[tid] = av;
            mul_s[tid] = mulp[mul_per_b ? (b * Hd + nb0 + nl) : (nb0 + nl)];
        }
        if (tid < 128) rowacc[tid] = 0.f;
    }

    auto load_tiles = [&](int st, int k0) {
        const uint32_t sA = sb + st * 32768;
        const uint32_t sB = sA + 16384;
#pragma unroll
        for (int i = 0; i < 4; i++) {
            int c = tid + (i << 8);
            int row = c >> 3, col = (c & 7) << 4;
            cpa16(sA + SWZ(row * 128 + col),
                  Ag + (size_t)(row0 + row) * ldaL + k0 + col);
        }
#pragma unroll
        for (int i = 0; i < 4; i++) {
            int c = tid + (i << 8);
            int row = c >> 3, col = (c & 7) << 4;
            int n = nb0 + row;
            cpa16z(sB + SWZ(row * 128 + col),
                   Bg + (size_t)n * ldbL + k0 + col, (n < NbL) ? 16 : 0);
        }
    };

    float acc[2][8][4];
#pragma unroll
    for (int t = 0; t < 2; t++)
#pragma unroll
        for (int j = 0; j < 8; j++)
#pragma unroll
            for (int q = 0; q < 4; q++) acc[t][j][q] = 0.f;

    if (L > 0) { load_tiles(0, kc0 * 128); CPCOMMIT(); }
    if (L > 1) { load_tiles(1, (kc0 + 1) * 128); CPCOMMIT(); }

    for (int lt = 0; lt < L; lt++) {
        if (lt + 2 < L) {
            load_tiles((lt + 2) % 3, (kc0 + lt + 2) * 128);
            CPCOMMIT();
            asm volatile("cp.async.wait_group 2;" ::: "memory");
        } else if (lt + 1 < L) {
            asm volatile("cp.async.wait_group 1;" ::: "memory");
        } else {
            asm volatile("cp.async.wait_group 0;" ::: "memory");
        }
        __syncthreads();
        const uint32_t As_b = sb + (lt % 3) * 32768;
        const uint32_t Bs_b = As_b + 16384;
#pragma unroll
        for (int kc = 0; kc < 4; kc++) {
            uint32_t af[2][4];
#pragma unroll
            for (int t = 0; t < 2; t++) {
                int row  = warpM * 32 + t * 16 + (lane & 15);
                int bcol = kc * 32 + ((lane >> 4) << 4);
                ldmx4(af[t], As_b + SWZ(row * 128 + bcol));
            }
            uint32_t bfr[4][4];
#pragma unroll
            for (int g = 0; g < 4; g++) {
                int row  = warpN * 64 + g * 16 + (lane & 7) + ((lane >> 4) << 3);
                int bcol = kc * 32 + (((lane >> 3) & 1) << 4);
                ldmx4(bfr[g], Bs_b + SWZ(row * 128 + bcol));
            }
#pragma unroll
            for (int t = 0; t < 2; t++)
#pragma unroll
                for (int g = 0; g < 4; g++) {
                    mma8(acc[t][2*g],   af[t], &bfr[g][0]);
                    mma8(acc[t][2*g+1], af[t], &bfr[g][2]);
                }
        }
        __syncthreads();
    }
    __syncthreads();   // covers L==0 (add_s/rowacc visibility)

    if (isGen) {
#pragma unroll
        for (int t = 0; t < 2; t++) {
            int r0 = row0 + warpM * 32 + t * 16 + (lane >> 2);
#pragma unroll
            for (int j = 0; j < 8; j++) {
                int c = nb0 + warpN * 64 + j * 8 + ((lane & 3) << 1);
                if (c < NbL) {
                    float b0v = add_s[c - nb0], b1v = add_s[c + 1 - nb0];
                    Co[(size_t)r0 * ldc + c]         = acc[t][j][0] * SC8 + b0v;
                    Co[(size_t)r0 * ldc + c + 1]     = acc[t][j][1] * SC8 + b1v;
                    Co[(size_t)(r0+8) * ldc + c]     = acc[t][j][2] * SC8 + b0v;
                    Co[(size_t)(r0+8) * ldc + c + 1] = acc[t][j][3] * SC8 + b1v;
                }
            }
        }
    } else {
        float rs[4] = {0.f, 0.f, 0.f, 0.f};
#pragma unroll
        for (int t = 0; t < 2; t++) {
            int bi = (warpM * 32 + t * 16) / Tdim;
            const float* aS = add_s + bi * 128;
            const float* mS = mul_s + bi * 128;
#pragma unroll
            for (int j = 0; j < 8; j++) {
                int n = warpN * 64 + j * 8 + ((lane & 3) << 1);
                rs[t*2+0] += tanh_f(acc[t][j][0] * SC8 + aS[n])   * mS[n]
                           + tanh_f(acc[t][j][1] * SC8 + aS[n+1]) * mS[n+1];
                rs[t*2+1] += tanh_f(acc[t][j][2] * SC8 + aS[n])   * mS[n]
                           + tanh_f(acc[t][j][3] * SC8 + aS[n+1]) * mS[n+1];
            }
        }
#pragma unroll
        for (int q = 0; q < 4; q++) {
            rs[q] += __shfl_xor_sync(0xffffffffu, rs[q], 1);
            rs[q] += __shfl_xor_sync(0xffffffffu, rs[q], 2);
        }
        if ((lane & 3) == 0) {
#pragma unroll
            for (int t = 0; t < 2; t++) {
                int rloc = warpM * 32 + t * 16 + (lane >> 2);
                atomicAdd(&rowacc[rloc],     rs[t*2+0]);
                atomicAdd(&rowacc[rloc + 8], rs[t*2+1]);
            }
        }
        __syncthreads();
        if (tid < 128)
            Co[(size_t)(nb0 >> 7) * Pstride + row0 + tid] = rowacc[tid];
    }
}

// ---------------- fused f32 -> e4m3(x16) conversion, 10 jobs ----------------
struct CJob { const float* src; uint8_t* dst; int rows, cols, lds, coff, ldd; };
struct CJobs { CJob j[10]; };

__global__ void __launch_bounds__(256)
conv_all(CJobs js)
{
    CJob J = js.j[blockIdx.y];
    const int w8 = J.ldd >> 3;
    const int nch = J.rows * w8;
    for (int i = blockIdx.x * 256 + threadIdx.x; i < nch; i += gridDim.x * 256) {
        int r = i / w8, c8 = (i - r * w8) << 3;
        uint32_t o0 = 0, o1 = 0;
        if (c8 < J.cols) {
            const float* s = J.src + (size_t)r * J.lds + J.coff + c8;
            float4 f0 = *(const float4*)s;
            float4 f1 = *(const float4*)(s + 4);
            o0 = (uint32_t)cvt2_e4m3(f0.x*16.f, f0.y*16.f)
               | ((uint32_t)cvt2_e4m3(f0.z*16.f, f0.w*16.f) << 16);
            o1 = (uint32_t)cvt2_e4m3(f1.x*16.f, f1.y*16.f)
               | ((uint32_t)cvt2_e4m3(f1.z*16.f, f1.w*16.f) << 16);
        }
        *(uint2*)(J.dst + (size_t)r * J.ldd + c8) = make_uint2(o0, o1);
    }
}

// ---------------- reductions ----------------
__device__ __forceinline__ float block_reduce_max(float val, float* red) {
    int tid = threadIdx.x, nw = blockDim.x >> 5;
    for (int o = 16; o; o >>= 1) val = fmaxf(val, __shfl_down_sync(0xffffffffu, val, o));
    if ((tid & 31) == 0) red[tid >> 5] = val;
    __syncthreads();
    if (tid < 32) {
        val = (tid < nw) ? red[tid] : -3.0e38f;
        for (int o = 16; o; o >>= 1) val = fmaxf(val, __shfl_down_sync(0xffffffffu, val, o));
        if (tid == 0) red[0] = val;
    }
    __syncthreads();
    val = red[0]; __syncthreads();
    return val;
}
__device__ __forceinline__ float block_reduce_sum(float val, float* red) {
    int tid = threadIdx.x, nw = blockDim.x >> 5;
    for (int o = 16; o; o >>= 1) val += __shfl_down_sync(0xffffffffu, val, o);
    if ((tid & 31) == 0) red[tid >> 5] = val;
    __syncthreads();
    if (tid < 32) {
        val = (tid < nw) ? red[tid] : 0.f;
        for (int o = 16; o; o >>= 1) val += __shfl_down_sync(0xffffffffu, val, o);
        if (tid == 0) red[0] = val;
    }
    __syncthreads();
    val = red[0]; __syncthreads();
    return val;
}

// masked softmax + ctx (z<3) + embedding/db/pad (z==3); grid (Bdim,1,4), 512 thr.
__global__ void __launch_bounds__(512)
softmax3_k(const float* __restrict__ score4,
           const int* __restrict__ ids_u, const int* __restrict__ ids_b,
           const int* __restrict__ ids_p,
           const uint8_t* __restrict__ e_u, const uint8_t* __restrict__ e_b,
           const uint8_t* __restrict__ e_p,
           uint8_t* __restrict__ X8,
           const int* __restrict__ w, const float* __restrict__ emb,
           const float* __restrict__ db)
{
    const int b = blockIdx.x, z = blockIdx.z, tid = threadIdx.x;
    if (z == 3) {
        int widx = w[b];
        if (tid < 256) {
            const float* e = emb + (size_t)widx * Hd + (tid << 1);
            *(uint16_t*)(X8 + (size_t)b * XP2 + (tid << 1)) =
                cvt2_e4m3(e[0] * 16.f, e[1] * 16.f);
        } else if (tid < 256 + PTRd/2) {
            int i = (tid - 256) << 1;
            const float* d = db + b * PTRd + i;
            *(uint16_t*)(X8 + (size_t)b * XP2 + 2048 + i) =
                cvt2_e4m3(d[0] * 16.f, d[1] * 16.f);
        } else if (tid < 256 + PTRd/2 + (XP2 - XR)/2) {
            int i = (tid - 256 - PTRd/2) << 1;
            *(uint16_t*)(X8 + (size_t)b * XP2 + XR + i) = 0;
        }
        return;
    }

    int T, soff; const int* ids; const uint8_t* enc;
    if (z == 0)      { T = TU; ids = ids_u; enc = e_u; soff = 0; }
    else if (z == 1) { T = TB; ids = ids_b; enc = e_b; soff = Bdim*TU; }
    else             { T = TP; ids = ids_p; enc = e_p; soff = Bdim*(TU+TB); }

    __shared__ float aw[TU];
    __shared__ float red[32];
    __shared__ float part[8 * 512];

    float sv = -3.0e38f;
    if (tid < T) {
        int idx = soff + b * T + tid;
        float s = score4[idx] + score4[BTOT + idx]
                + score4[2*BTOT + idx] + score4[3*BTOT + idx];
        if (ids[b * T + tid] == 0) s = NEGV;
        aw[tid] = s; sv = s;
    }
    float m = block_reduce_max(sv, red);
    float e = 0.f;
    if (tid < T) { e = __expf(aw[tid] - m); aw[tid] = e; }
    float ssum = block_reduce_sum(e, red);
    float inv = 1.f / ssum;

    const int tg = tid >> 6;              // 8 t-groups
    const int hc = (tid & 63) << 3;       // 8 h-cols per thread
    float c[8];
#pragma unroll
    for (int k = 0; k < 8; k++) c[k] = 0.f;
    const uint8_t* eb = enc + (size_t)b * T * Hd + hc;
#pragma unroll 4
    for (int t = tg; t < T; t += 8) {
        uint2 v = *(const uint2*)(eb + (size_t)t * Hd);
        float2 f0 = cvt_e4m3_2f((uint16_t)(v.x & 0xffffu));
        float2 f1 = cvt_e4m3_2f((uint16_t)(v.x >> 16));
        float2 f2 = cvt_e4m3_2f((uint16_t)(v.y & 0xffffu));
        float2 f3 = cvt_e4m3_2f((uint16_t)(v.y >> 16));
        float wv = aw[t] * inv;
        c[0] = fmaf(wv, f0.x, c[0]); c[1] = fmaf(wv, f0.y, c[1]);
        c[2] = fmaf(wv, f1.x, c[2]); c[3] = fmaf(wv, f1.y, c[3]);
        c[4] = fmaf(wv, f2.x, c[4]); c[5] = fmaf(wv, f2.y, c[5]);
        c[6] = fmaf(wv, f3.x, c[6]); c[7] = fmaf(wv, f3.y, c[7]);
    }
#pragma unroll
    for (int k = 0; k < 8; k++) part[tg * 512 + hc + k] = c[k];
    __syncthreads();
    float s = part[tid];
#pragma unroll
    for (int g = 1; g < 8; g++) s += part[g * 512 + tid];
    part[tid] = s;
    __syncthreads();
    if (tid < 128) {
        int h0 = tid << 2;
        uint32_t o = (uint32_t)cvt2_e4m3(part[h0], part[h0+1])
                   | ((uint32_t)cvt2_e4m3(part[h0+2], part[h0+3]) << 16);
        *(uint32_t*)(X8 + (size_t)b * XP2 + Hd * (z + 1) + h0) = o;
    }
}

// gate: sums 3 K-partials of gi and gh
__global__ void gate_k(const float* __restrict__ gi, const float* __restrict__ gh,
                       const float* __restrict__ h0, float* __restrict__ hnew,
                       uint8_t* __restrict__ hn8)
{
    int b = blockIdx.x, h = threadIdx.x;
    int i0 = b*G3H + h, i1 = b*G3H + Hd + h, i2 = b*G3H + 2*Hd + h;
    float ir  = gi[i0] + gi[GIS + i0] + gi[2*GIS + i0];
    float iz  = gi[i1] + gi[GIS + i1] + gi[2*GIS + i1];
    float inn = gi[i2] + gi[GIS + i2] + gi[2*GIS + i2];
    float hr  = gh[i0] + gh[GIS + i0] + gh[2*GIS + i0];
    float hz  = gh[i1] + gh[GIS + i1] + gh[2*GIS + i1];
    float hn  = gh[i2] + gh[GIS + i2] + gh[2*GIS + i2];
    float rr = 1.f / (1.f + __expf(-(ir + hr)));
    float z  = 1.f / (1.f + __expf(-(iz + hz)));
    float n  = tanhf(inn + rr * hn);
    float v  = (1.f - z) * n + z * h0[b*Hd + h];
    hnew[b*Hd + h] = v;
    uint16_t p = cvt2_e4m3(v * 16.f, 0.f);
    hn8[b*Hd + h] = (uint8_t)(p & 0xff);
}

// final: build cps in smem from cpraw4 partials, single-exp log-softmax + OOV
__global__ void __launch_bounds__(1024)
final_k(const float* __restrict__ gen, const float* __restrict__ cpraw4,
        const int* __restrict__ bids, const int* __restrict__ nounk,
        float* __restrict__ out)
{
    const int b = blockIdx.x, tid = threadIdx.x;
    const float* gb = gen + (size_t)b * Vd;
    __shared__ float red[32];
    __shared__ float adds[VOOVd - Vd];
    __shared__ float cps_s[CPSW];
    __shared__ float eg_s[Vd];

    for (int i = tid; i < CPSW; i += 1024) cps_s[i] = 0.f;
    __syncthreads();
    if (tid < TB) {
        int idx = b * TB + tid;
        float val = cpraw4[idx] + cpraw4[PCP + idx]
                  + cpraw4[2*PCP + idx] + cpraw4[3*PCP + idx];
        if (bids[idx] == 0) val = NEGV;
        int nk = nounk[idx];
        int col = (nk < Vd) ? nk : (Vd + tid);
        atomicAdd(&cps_s[col], val);
    }
    __syncthreads();

    float m = -3.0e38f;
    for (int i = tid; i < Vd;   i += 1024) m = fmaxf(m, gb[i]);
    for (int i = tid; i < CPSW; i += 1024) m = fmaxf(m, cps_s[i]);
    m = block_reduce_max(m, red);

    float s = 0.f;
    for (int i = tid; i < Vd; i += 1024) {
        float e = __expf(gb[i] - m);
        eg_s[i] = e; s += e;
    }
    for (int i = tid; i < CPSW; i += 1024) {
        float e = __expf(cps_s[i] - m);
        cps_s[i] = e; s += e;
    }
    s = block_reduce_sum(s, red);
    float logS = __logf(s);

    for (int i = tid; i < Vd; i += 1024)
        out[(size_t)b*VOOVd + i] = __logf(eg_s[i] + cps_s[i]) - logS;

    for (int i = tid; i < (VOOVd - Vd); i += 1024) adds[i] = 0.f;
    __syncthreads();
    if (tid < TB) {
        int nk = nounk[b*TB + tid];
        if (nk >= Vd) atomicAdd(&adds[nk - Vd], cps_s[Vd + tid] / s);
    }
    __syncthreads();
    for (int i = tid; i < (VOOVd - Vd); i += 1024) {
        float a = adds[i];
        out[(size_t)b*VOOVd + Vd + i] = (a > 0.f) ? __logf(fmaxf(a, 1e-38f)) : NEGV;
    }
}

// =============================== host ======================================
#define SMEMSZ (SM_EPI + 2560)

extern "C" void kernel_launch(void* const* d_in, const int* in_sizes, int n_in,
                              void* d_out, int out_size)
{
    (void)in_sizes; (void)n_in; (void)out_size;
    const int*   dec_last_w = (const int*)  d_in[0];
    const float* dec_last_h = (const float*)d_in[1];
    const float* usdx_h     = (const float*)d_in[2];
    const float* bspn_h     = (const float*)d_in[3];
    const float* pvaspn_h   = (const float*)d_in[4];
    const float* db         = (const float*)d_in[5];
    const int*   usdx_ids   = (const int*)  d_in[6];
    const int*   bspn_ids   = (const int*)  d_in[7];
    const int*   pvaspn_ids = (const int*)  d_in[8];
    const int*   bspn_nounk = (const int*)  d_in[9];
    /* d_in[10] bspn_onehot unused */
    const float* emb_table  = (const float*)d_in[11];
    const float* attn_W     = (const float*)d_in[12];
    const float* attn_b     = (const float*)d_in[13];
    const float* v_w        = (const float*)d_in[14];
    const float* Wcopy_w    = (const float*)d_in[15];
    const float* Wcopy_b    = (const float*)d_in[16];
    const float* Wgen_w     = (const float*)d_in[17];
    const float* Wgen_b     = (const float*)d_in[18];
    const float* W_ih       = (const float*)d_in[19];
    const float* W_hh       = (const float*)d_in[20];
    const float* b_ih       = (const float*)d_in[21];
    const float* b_hh       = (const float*)d_in[22];
    float* out = (float*)d_out;

    float *pre1,*score4,*gi,*gh,*hnew,*gen,*cpraw4;
    uint8_t *W8a,*W8b,*W8c,*W8hh,*W8ih,*W8gn,*h8,*u8,*b8,*p8,*X8,*hn8;
    cudaGetSymbolAddress((void**)&pre1,   g_pre1);
    cudaGetSymbolAddress((void**)&score4, g_score4);
    cudaGetSymbolAddress((void**)&gi,     g_gi);
    cudaGetSymbolAddress((void**)&gh,     g_gh);
    cudaGetSymbolAddress((void**)&hnew,   g_hnew);
    cudaGetSymbolAddress((void**)&gen,    g_gen);
    cudaGetSymbolAddress((void**)&cpraw4, g_cpraw4);
    cudaGetSymbolAddress((void**)&W8a,    g_W8a);
    cudaGetSymbolAddress((void**)&W8b,    g_W8b);
    cudaGetSymbolAddress((void**)&W8c,    g_W8c);
    cudaGetSymbolAddress((void**)&W8hh,   g_W8hh);
    cudaGetSymbolAddress((void**)&W8ih,   g_W8ih);
    cudaGetSymbolAddress((void**)&W8gn,   g_W8gn);
    cudaGetSymbolAddress((void**)&h8,     g_h8);
    cudaGetSymbolAddress((void**)&u8,     g_u8);
    cudaGetSymbolAddress((void**)&b8,     g_b8);
    cudaGetSymbolAddress((void**)&p8,     g_p8);
    cudaGetSymbolAddress((void**)&X8,     g_X8);
    cudaGetSymbolAddress((void**)&hn8,    g_hn8);

    cudaFuncSetAttribute(gemm8<0,1,2>, cudaFuncAttributeMaxDynamicSharedMemorySize, SMEMSZ);
    cudaFuncSetAttribute(gemm8<0,2,3>, cudaFuncAttributeMaxDynamicSharedMemorySize, SMEMSZ);
    cudaFuncSetAttribute(gemm8<1,3,1>, cudaFuncAttributeMaxDynamicSharedMemorySize, SMEMSZ);
    cudaFuncSetAttribute(gemm8<3,4,1>, cudaFuncAttributeMaxDynamicSharedMemorySize, SMEMSZ);

    // 1: all f32 -> fp8(x16) conversions
    CJobs js;
    js.j[0] = { attn_W,     W8a,  Hd,      Hd, 2*Hd, 0,  Hd  };
    js.j[1] = { attn_W,     W8b,  Hd,      Hd, 2*Hd, Hd, Hd  };
    js.j[2] = { Wcopy_w,    W8c,  Hd,      Hd, Hd,   0,  Hd  };
    js.j[3] = { W_hh,       W8hh, G3H,     Hd, Hd,   0,  Hd  };
    js.j[4] = { W_ih,       W8ih, G3H,     XR, XR,   0,  XP2 };
    js.j[5] = { Wgen_w,     W8gn, Vd,      Hd, Hd,   0,  Hd  };
    js.j[6] = { dec_last_h, h8,   Bdim,    Hd, Hd,   0,  Hd  };
    js.j[7] = { usdx_h,     u8,   Bdim*TU, Hd, Hd,   0,  Hd  };
    js.j[8] = { bspn_h,     b8,   Bdim*TB, Hd, Hd,   0,  Hd  };
    js.j[9] = { pvaspn_h,   p8,   Bdim*TP, Hd, Hd,   0,  Hd  };
    conv_all<<<dim3(1024, 10), 256>>>(js);

    // 2: pre1 = h0 @ Wa^T + attn_b  (split-K x2, partial stores)
    gemm8<0,1,2><<<dim3(1,4,2), 256, SMEMSZ>>>(h8, nullptr, nullptr, Hd, 4,
        W8a, Hd, Hd, attn_b, 0, nullptr, 0, 1, pre1, nullptr, nullptr, Hd, 0,
        nullptr, nullptr, 0, 0, PRE1S);

    // 3: ALL attention scores -> score4 partials (pre1 = sum of 2 K-partials)
    gemm8<1,3,1><<<dim3(448,4), 256, SMEMSZ>>>(u8, b8, p8, Hd, 4,
        W8b, Hd, Hd, pre1, 1, v_w, 0, 0,
        score4, score4 + Bdim*TU, score4 + Bdim*(TU+TB), 0, BTOT,
        nullptr, nullptr, 0, 0, 0, 2, PRE1S);

    // 4: softmax + ctx (+ emb/db/pad as z=3)
    softmax3_k<<<dim3(Bdim,1,4), 512>>>(score4, usdx_ids, bspn_ids, pvaspn_ids,
                                        u8, b8, p8, X8, dec_last_w, emb_table, db);

    // 5: gi + gh merged, split-K x3 (partial stores; gate sums)
    gemm8<0,2,3><<<dim3(2,12,3), 256, SMEMSZ>>>(X8, h8, nullptr, XP2, 17,
        W8ih, XP2, G3H, b_ih, 0, nullptr, 0, 1, gi, gh, nullptr, G3H, 0,
        W8hh, b_hh, Hd, 4, GIS);

    // 6: gate (sums 3 partials)
    gate_k<<<Bdim, Hd>>>(gi, gh, dec_last_h, hnew, hn8);

    // 7: merged gen (24 blocks) + cpraw (512 blocks), NS=4
    gemm8<3,4,1><<<536, 256, SMEMSZ>>>(hn8, b8, nullptr, Hd, 4,
        W8gn, Hd, Vd, Wgen_b, 0, hnew, 1, TB, gen, cpraw4, nullptr, Vd, PCP,
        W8c, Wcopy_b, Hd, 4);

    // 8: final (cps built in smem; scatter fused; single-exp)
    final_k<<<Bdim, 1024>>>(gen, cpraw4, bspn_ids, bspn_nounk, out);
}